// round 1
// baseline (speedup 1.0000x reference)
#include <cuda_runtime.h>
#include <math.h>

// Problem constants (fixed by the reference)
#define IMG_W 256
#define IMG_H 256
#define MAXN  512
#define HW    (IMG_W * IMG_H)        // 65536
#define FX    256.0f                  // W / (2 * tanfovx)
#define FY    256.0f
#define LIMX  0.65f                   // 1.3 * tanfovx
#define LIMY  0.65f

// Output layout in d_out (float32): color [3*HW], radii [MAXN], invd [HW]
#define OFF_RADII (3 * HW)
#define OFF_INVD  (3 * HW + MAXN)

// Per-gaussian packed record: 64 bytes, float4-aligned for coalesced copies.
struct __align__(16) G {
    float px, py, ca, cb;     // center + conic xx, xy
    float cc, op, cr, cg;     // conic yy, opacity, color r,g
    float cbl, invd, x0, x1;  // color b, 1/max(depth,1e-6), bbox x
    float y0, y1, pad0, pad1; // bbox y
};

__device__ G   g_list[MAXN];   // depth-sorted, compacted contributing gaussians
__device__ int g_count_dev;

// ---------------------------------------------------------------------------
// Kernel 1: preprocess (project, conic, radii, bbox), bitonic depth sort,
// order-preserving compaction. One CTA of 512 threads.
// ---------------------------------------------------------------------------
__global__ __launch_bounds__(MAXN)
void prep_kernel(const float* __restrict__ means3D,
                 const float* __restrict__ opac,
                 const float* __restrict__ colors,
                 const float* __restrict__ scales,
                 const float* __restrict__ rots,
                 const float* __restrict__ Vm,   // 4x4 row-major
                 const float* __restrict__ Pm,   // 4x4 row-major
                 float* __restrict__ out_radii,
                 int n)
{
    __shared__ G     s_pre[MAXN];    // 32 KB
    __shared__ float s_key[MAXN];
    __shared__ int   s_idx[MAXN];
    __shared__ int   s_flag[MAXN];
    __shared__ int   s_scan[MAXN];

    const int tid = threadIdx.x;

    float depth = 3.0e38f;
    int contrib = 0;
    G g;

    if (tid < n) {
        const float m0 = means3D[3 * tid + 0];
        const float m1 = means3D[3 * tid + 1];
        const float m2 = means3D[3 * tid + 2];

        // view transform t = V * [m,1]
        const float t0 = Vm[0] * m0 + Vm[1] * m1 + Vm[2]  * m2 + Vm[3];
        const float t1 = Vm[4] * m0 + Vm[5] * m1 + Vm[6]  * m2 + Vm[7];
        const float t2 = Vm[8] * m0 + Vm[9] * m1 + Vm[10] * m2 + Vm[11];
        depth = t2;

        // clip = P * [m,1]
        const float c0 = Pm[0]  * m0 + Pm[1]  * m1 + Pm[2]  * m2 + Pm[3];
        const float c1 = Pm[4]  * m0 + Pm[5]  * m1 + Pm[6]  * m2 + Pm[7];
        const float c3 = Pm[12] * m0 + Pm[13] * m1 + Pm[14] * m2 + Pm[15];
        const float pw = 1.0f / (c3 + 1e-7f);
        const float px = ((c0 * pw + 1.0f) * (float)IMG_W - 1.0f) * 0.5f;
        const float py = ((c1 * pw + 1.0f) * (float)IMG_H - 1.0f) * 0.5f;

        // quaternion -> rotation
        const float q0r = rots[4 * tid + 0];
        const float q1r = rots[4 * tid + 1];
        const float q2r = rots[4 * tid + 2];
        const float q3r = rots[4 * tid + 3];
        const float qn = 1.0f / sqrtf(q0r*q0r + q1r*q1r + q2r*q2r + q3r*q3r);
        const float w = q0r * qn, x = q1r * qn, y = q2r * qn, z = q3r * qn;

        const float r00 = 1.0f - 2.0f * (y*y + z*z);
        const float r01 = 2.0f * (x*y - w*z);
        const float r02 = 2.0f * (x*z + w*y);
        const float r10 = 2.0f * (x*y + w*z);
        const float r11 = 1.0f - 2.0f * (x*x + z*z);
        const float r12 = 2.0f * (y*z - w*x);
        const float r20 = 2.0f * (x*z - w*y);
        const float r21 = 2.0f * (y*z + w*x);
        const float r22 = 1.0f - 2.0f * (x*x + y*y);

        const float s0 = scales[3 * tid + 0];
        const float s1 = scales[3 * tid + 1];
        const float s2 = scales[3 * tid + 2];

        // M = R * diag(s); cov3d = M M^T (symmetric)
        const float M00 = r00*s0, M01 = r01*s1, M02 = r02*s2;
        const float M10 = r10*s0, M11 = r11*s1, M12 = r12*s2;
        const float M20 = r20*s0, M21 = r21*s1, M22 = r22*s2;
        const float C00 = M00*M00 + M01*M01 + M02*M02;
        const float C01 = M00*M10 + M01*M11 + M02*M12;
        const float C02 = M00*M20 + M01*M21 + M02*M22;
        const float C11 = M10*M10 + M11*M11 + M12*M12;
        const float C12 = M10*M20 + M11*M21 + M12*M22;
        const float C22 = M20*M20 + M21*M21 + M22*M22;

        // Jacobian
        const float tz = depth;
        const float txc = fminf(fmaxf(t0 / tz, -LIMX), LIMX) * tz;
        const float tyc = fminf(fmaxf(t1 / tz, -LIMY), LIMY) * tz;
        const float j00 = FX / tz;
        const float j02 = -FX * txc / (tz * tz);
        const float j11 = FY / tz;
        const float j12 = -FY * tyc / (tz * tz);

        // Tm = J * V[:3,:3]  (rows 0,1 only; row 2 of J is zero)
        const float T00 = j00 * Vm[0] + j02 * Vm[8];
        const float T01 = j00 * Vm[1] + j02 * Vm[9];
        const float T02 = j00 * Vm[2] + j02 * Vm[10];
        const float T10 = j11 * Vm[4] + j12 * Vm[8];
        const float T11 = j11 * Vm[5] + j12 * Vm[9];
        const float T12 = j11 * Vm[6] + j12 * Vm[10];

        // cov2d = Tm * C * Tm^T
        const float u0 = C00*T00 + C01*T01 + C02*T02;
        const float u1 = C01*T00 + C11*T01 + C12*T02;
        const float u2 = C02*T00 + C12*T01 + C22*T02;
        const float cxx = T00*u0 + T01*u1 + T02*u2;
        const float cxy = T10*u0 + T11*u1 + T12*u2;
        const float v0 = C00*T10 + C01*T11 + C02*T12;
        const float v1 = C01*T10 + C11*T11 + C12*T12;
        const float v2 = C02*T10 + C12*T11 + C22*T12;
        const float cyy = T10*v0 + T11*v1 + T12*v2;

        const float a = cxx + 0.3f;
        const float b = cxy;
        const float c = cyy + 0.3f;
        const float det = a * c - b * b;
        const float inv_det = 1.0f / ((det != 0.0f) ? det : 1.0f);
        const float ca = c * inv_det;
        const float cbv = -b * inv_det;
        const float cc = a * inv_det;
        const float mid = 0.5f * (a + c);
        const float lam = mid + sqrtf(fmaxf(mid * mid - det, 0.1f));
        out_radii[tid] = ceilf(3.0f * sqrtf(lam));   // int32 radii cast to float

        const int valid = (depth > 0.2f) && (det > 0.0f);
        const float op = opac[tid];

        // alpha >= 1/255 with power<=0 implies q <= qmax = 2*ln(255*op).
        // Extent of {q <= qmax} along x is sqrt(qmax * a) (conic det identity),
        // along y sqrt(qmax * c). +1px margin; exact checks run per-pixel.
        const float qmax = 2.0f * logf(255.0f * op);
        contrib = valid && (qmax > 0.0f);

        g.px = px; g.py = py; g.ca = ca; g.cb = cbv;
        g.cc = cc; g.op = op;
        g.cr  = colors[3 * tid + 0];
        g.cg  = colors[3 * tid + 1];
        g.cbl = colors[3 * tid + 2];
        g.invd = 1.0f / fmaxf(depth, 1e-6f);
        if (contrib) {
            const float dxm = sqrtf(qmax * a) + 1.0f;
            const float dym = sqrtf(qmax * c) + 1.0f;
            g.x0 = px - dxm; g.x1 = px + dxm;
            g.y0 = py - dym; g.y1 = py + dym;
            if (g.x1 < 0.0f || g.x0 > (float)(IMG_W - 1) ||
                g.y1 < 0.0f || g.y0 > (float)(IMG_H - 1))
                contrib = 0;
        } else {
            g.x0 = g.x1 = g.y0 = g.y1 = 0.0f;
        }
        g.pad0 = g.pad1 = 0.0f;
        s_pre[tid] = g;
    }
    s_flag[tid] = contrib;
    s_key[tid]  = depth;
    s_idx[tid]  = tid;
    __syncthreads();

    // Bitonic sort ascending by (depth, idx) — stable-equivalent.
    for (int k = 2; k <= MAXN; k <<= 1) {
        for (int j = k >> 1; j > 0; j >>= 1) {
            const int ixj = tid ^ j;
            if (ixj > tid) {
                const float ka = s_key[tid], kb = s_key[ixj];
                const int   ia = s_idx[tid], ib = s_idx[ixj];
                const bool a_gt_b = (ka > kb) || (ka == kb && ia > ib);
                const bool up = ((tid & k) == 0);
                if (up ? a_gt_b : !a_gt_b) {
                    s_key[tid] = kb; s_key[ixj] = ka;
                    s_idx[tid] = ib; s_idx[ixj] = ia;
                }
            }
            __syncthreads();
        }
    }

    // Order-preserving compaction of contributing gaussians.
    const int src = s_idx[tid];
    const int fl = s_flag[src];
    s_scan[tid] = fl;
    __syncthreads();
    for (int off = 1; off < MAXN; off <<= 1) {
        const int v = (tid >= off) ? s_scan[tid - off] : 0;
        __syncthreads();
        s_scan[tid] += v;
        __syncthreads();
    }
    if (fl)
        g_list[s_scan[tid] - 1] = s_pre[src];
    if (tid == MAXN - 1)
        g_count_dev = s_scan[MAXN - 1];
}

// ---------------------------------------------------------------------------
// Kernel 2: tiled rasterization. 16x16 px tile per CTA (256 threads).
// Per-chunk tile cull with order-preserving prefix-sum compaction, then
// per-pixel front-to-back alpha blend with the exact reference keep tests.
// ---------------------------------------------------------------------------
__global__ __launch_bounds__(256)
void raster_kernel(const float* __restrict__ bg,
                   const float* __restrict__ mask,
                   float* __restrict__ out)
{
    __shared__ G   sg[256];       // 16 KB
    __shared__ int s_scan[256];
    __shared__ int slist[256];

    const int t = threadIdx.x;
    const int pxi = blockIdx.x * 16 + (t & 15);
    const int pyi = blockIdx.y * 16 + (t >> 4);
    const float xf = (float)pxi;
    const float yf = (float)pyi;

    const float tx0f = (float)(blockIdx.x * 16);
    const float tx1f = tx0f + 15.0f;
    const float ty0f = (float)(blockIdx.y * 16);
    const float ty1f = ty0f + 15.0f;

    float Tacc = 1.0f;
    float cr = 0.0f, cg = 0.0f, cbl = 0.0f, iv = 0.0f;

    const int count = g_count_dev;

    for (int base = 0; base < count; base += 256) {
        int fl = 0;
        const int gi = base + t;
        if (gi < count) {
            float4*       dst = reinterpret_cast<float4*>(&sg[t]);
            const float4* src = reinterpret_cast<const float4*>(&g_list[gi]);
            dst[0] = src[0]; dst[1] = src[1]; dst[2] = src[2]; dst[3] = src[3];
            const G& g = sg[t];
            fl = (g.x1 >= tx0f) && (g.x0 <= tx1f) &&
                 (g.y1 >= ty0f) && (g.y0 <= ty1f);
        }
        s_scan[t] = fl;
        __syncthreads();
        for (int off = 1; off < 256; off <<= 1) {
            const int v = (t >= off) ? s_scan[t - off] : 0;
            __syncthreads();
            s_scan[t] += v;
            __syncthreads();
        }
        const int cnt = s_scan[255];
        if (fl)
            slist[s_scan[t] - 1] = t;
        __syncthreads();

        for (int j = 0; j < cnt; j++) {
            const G& g = sg[slist[j]];
            const float dx = xf - g.px;
            const float dy = yf - g.py;
            const float power = -0.5f * (g.ca * dx * dx + g.cc * dy * dy)
                                - g.cb * dx * dy;
            if (power <= 0.0f) {
                const float alpha = fminf(0.99f, g.op * expf(power));
                if (alpha >= (1.0f / 255.0f)) {
                    const float wgt = alpha * Tacc;
                    cr  += wgt * g.cr;
                    cg  += wgt * g.cg;
                    cbl += wgt * g.cbl;
                    iv  += wgt * g.invd;
                    Tacc *= (1.0f - alpha);
                }
            }
        }
        __syncthreads();
    }

    const int pix = pyi * IMG_W + pxi;
    const float mk = mask[pix];
    const float b0 = bg[0], b1 = bg[1], b2 = bg[2];
    out[pix]            = (cr  + Tacc * b0) * mk;
    out[HW + pix]       = (cg  + Tacc * b1) * mk;
    out[2 * HW + pix]   = (cbl + Tacc * b2) * mk;
    out[OFF_INVD + pix] = iv * mk;
}

// ---------------------------------------------------------------------------
extern "C" void kernel_launch(void* const* d_in, const int* in_sizes, int n_in,
                              void* d_out, int out_size)
{
    const float* means3D = (const float*)d_in[0];
    // d_in[1] = means2D (unused by the reference math)
    const float* opac    = (const float*)d_in[2];
    const float* colors  = (const float*)d_in[3];
    const float* scales  = (const float*)d_in[4];
    const float* rots    = (const float*)d_in[5];
    const float* Vm      = (const float*)d_in[6];
    const float* Pm      = (const float*)d_in[7];
    const float* bg      = (const float*)d_in[8];
    const float* mask    = (const float*)d_in[9];
    float* out = (float*)d_out;

    int n = in_sizes[0] / 3;
    if (n > MAXN) n = MAXN;

    prep_kernel<<<1, MAXN>>>(means3D, opac, colors, scales, rots, Vm, Pm,
                             out + OFF_RADII, n);
    raster_kernel<<<dim3(IMG_W / 16, IMG_H / 16), 256>>>(bg, mask, out);
}

// round 2
// speedup vs baseline: 1.4229x; 1.4229x over previous
#include <cuda_runtime.h>
#include <math.h>

// Problem constants (fixed by the reference)
#define IMG_W 256
#define IMG_H 256
#define MAXN  512
#define HW    (IMG_W * IMG_H)        // 65536
#define FX    256.0f                  // W / (2 * tanfovx)
#define FY    256.0f
#define LIMX  0.65f                   // 1.3 * tanfovx
#define LIMY  0.65f

// Output layout in d_out (float32): color [3*HW], radii [MAXN], invd [HW]
#define OFF_RADII (3 * HW)
#define OFF_INVD  (3 * HW + MAXN)

// Blend core: 48 bytes = 3 float4
//   f0 = (px, py, ca, cb)   f1 = (cc, op, cr, cg)   f2 = (cbl, invd, 0, 0)
struct __align__(16) GCore { float4 f0, f1, f2; };

__device__ float4             g_bbox[MAXN];   // (x0, x1, y0, y1)
__device__ GCore              g_core[MAXN];
__device__ unsigned long long g_skey[MAXN];   // (depth_bits<<18)|(orig_idx<<9)
__device__ int                g_count_dev;

// ---------------------------------------------------------------------------
// Kernel 1: per-gaussian preprocess + ballot compaction (NO sort).
// One CTA of 512 threads, 2 barriers.
// ---------------------------------------------------------------------------
__global__ __launch_bounds__(MAXN)
void prep_kernel(const float* __restrict__ means3D,
                 const float* __restrict__ opac,
                 const float* __restrict__ colors,
                 const float* __restrict__ scales,
                 const float* __restrict__ rots,
                 const float* __restrict__ Vm,   // 4x4 row-major
                 const float* __restrict__ Pm,   // 4x4 row-major
                 float* __restrict__ out_radii,
                 int n)
{
    __shared__ int s_cnt;
    const int tid = threadIdx.x;
    if (tid == 0) s_cnt = 0;
    __syncthreads();

    bool contrib = false;
    float depth = 0.0f;
    float px = 0.f, py = 0.f, ca = 0.f, cbv = 0.f, cc = 0.f, op = 0.f;
    float x0 = 0.f, x1 = 0.f, y0 = 0.f, y1 = 0.f;

    if (tid < n) {
        const float m0 = means3D[3 * tid + 0];
        const float m1 = means3D[3 * tid + 1];
        const float m2 = means3D[3 * tid + 2];

        // view transform t = V * [m,1]
        const float t0 = Vm[0] * m0 + Vm[1] * m1 + Vm[2]  * m2 + Vm[3];
        const float t1 = Vm[4] * m0 + Vm[5] * m1 + Vm[6]  * m2 + Vm[7];
        const float t2 = Vm[8] * m0 + Vm[9] * m1 + Vm[10] * m2 + Vm[11];
        depth = t2;

        // clip = P * [m,1]
        const float c0 = Pm[0]  * m0 + Pm[1]  * m1 + Pm[2]  * m2 + Pm[3];
        const float c1 = Pm[4]  * m0 + Pm[5]  * m1 + Pm[6]  * m2 + Pm[7];
        const float c3 = Pm[12] * m0 + Pm[13] * m1 + Pm[14] * m2 + Pm[15];
        const float pw = 1.0f / (c3 + 1e-7f);
        px = ((c0 * pw + 1.0f) * (float)IMG_W - 1.0f) * 0.5f;
        py = ((c1 * pw + 1.0f) * (float)IMG_H - 1.0f) * 0.5f;

        // quaternion -> rotation
        const float q0r = rots[4 * tid + 0];
        const float q1r = rots[4 * tid + 1];
        const float q2r = rots[4 * tid + 2];
        const float q3r = rots[4 * tid + 3];
        const float qn = 1.0f / sqrtf(q0r*q0r + q1r*q1r + q2r*q2r + q3r*q3r);
        const float w = q0r * qn, x = q1r * qn, y = q2r * qn, z = q3r * qn;

        const float r00 = 1.0f - 2.0f * (y*y + z*z);
        const float r01 = 2.0f * (x*y - w*z);
        const float r02 = 2.0f * (x*z + w*y);
        const float r10 = 2.0f * (x*y + w*z);
        const float r11 = 1.0f - 2.0f * (x*x + z*z);
        const float r12 = 2.0f * (y*z - w*x);
        const float r20 = 2.0f * (x*z - w*y);
        const float r21 = 2.0f * (y*z + w*x);
        const float r22 = 1.0f - 2.0f * (x*x + y*y);

        const float s0 = scales[3 * tid + 0];
        const float s1 = scales[3 * tid + 1];
        const float s2 = scales[3 * tid + 2];

        // M = R * diag(s); cov3d = M M^T (symmetric)
        const float M00 = r00*s0, M01 = r01*s1, M02 = r02*s2;
        const float M10 = r10*s0, M11 = r11*s1, M12 = r12*s2;
        const float M20 = r20*s0, M21 = r21*s1, M22 = r22*s2;
        const float C00 = M00*M00 + M01*M01 + M02*M02;
        const float C01 = M00*M10 + M01*M11 + M02*M12;
        const float C02 = M00*M20 + M01*M21 + M02*M22;
        const float C11 = M10*M10 + M11*M11 + M12*M12;
        const float C12 = M10*M20 + M11*M21 + M12*M22;
        const float C22 = M20*M20 + M21*M21 + M22*M22;

        // Jacobian
        const float tz = depth;
        const float txc = fminf(fmaxf(t0 / tz, -LIMX), LIMX) * tz;
        const float tyc = fminf(fmaxf(t1 / tz, -LIMY), LIMY) * tz;
        const float j00 = FX / tz;
        const float j02 = -FX * txc / (tz * tz);
        const float j11 = FY / tz;
        const float j12 = -FY * tyc / (tz * tz);

        // Tm = J * V[:3,:3]  (rows 0,1 only)
        const float T00 = j00 * Vm[0] + j02 * Vm[8];
        const float T01 = j00 * Vm[1] + j02 * Vm[9];
        const float T02 = j00 * Vm[2] + j02 * Vm[10];
        const float T10 = j11 * Vm[4] + j12 * Vm[8];
        const float T11 = j11 * Vm[5] + j12 * Vm[9];
        const float T12 = j11 * Vm[6] + j12 * Vm[10];

        // cov2d = Tm * C * Tm^T
        const float u0 = C00*T00 + C01*T01 + C02*T02;
        const float u1 = C01*T00 + C11*T01 + C12*T02;
        const float u2 = C02*T00 + C12*T01 + C22*T02;
        const float cxx = T00*u0 + T01*u1 + T02*u2;
        const float cxy = T10*u0 + T11*u1 + T12*u2;
        const float v0 = C00*T10 + C01*T11 + C02*T12;
        const float v1 = C01*T10 + C11*T11 + C12*T12;
        const float v2 = C02*T10 + C12*T11 + C22*T12;
        const float cyy = T10*v0 + T11*v1 + T12*v2;

        const float a = cxx + 0.3f;
        const float b = cxy;
        const float c = cyy + 0.3f;
        const float det = a * c - b * b;
        const float inv_det = 1.0f / ((det != 0.0f) ? det : 1.0f);
        ca  = c * inv_det;
        cbv = -b * inv_det;
        cc  = a * inv_det;
        const float mid = 0.5f * (a + c);
        const float lam = mid + sqrtf(fmaxf(mid * mid - det, 0.1f));
        out_radii[tid] = ceilf(3.0f * sqrtf(lam));   // int32 radii as float

        const bool valid = (depth > 0.2f) && (det > 0.0f);
        op = opac[tid];

        // keep (alpha>=1/255, power<=0) implies mahal^2 <= qmax = 2*ln(255*op);
        // x-extent of that set is sqrt(qmax*a) (conic determinant identity).
        const float qmax = 2.0f * logf(255.0f * op);
        contrib = valid && (qmax > 0.0f);
        if (contrib) {
            const float dxm = sqrtf(qmax * a) + 1.0f;
            const float dym = sqrtf(qmax * c) + 1.0f;
            x0 = px - dxm; x1 = px + dxm;
            y0 = py - dym; y1 = py + dym;
            if (x1 < 0.0f || x0 > (float)(IMG_W - 1) ||
                y1 < 0.0f || y0 > (float)(IMG_H - 1))
                contrib = false;
        }
    }

    // Ballot compaction (arbitrary order; order restored per-tile later).
    const unsigned m = __ballot_sync(0xffffffffu, contrib);
    const int lane = tid & 31;
    int wbase = 0;
    if (lane == 0 && m) wbase = atomicAdd(&s_cnt, __popc(m));
    wbase = __shfl_sync(0xffffffffu, wbase, 0);
    if (contrib) {
        const int pos = wbase + __popc(m & ((1u << lane) - 1u));
        g_bbox[pos] = make_float4(x0, x1, y0, y1);
        GCore gc;
        gc.f0 = make_float4(px, py, ca, cbv);
        gc.f1 = make_float4(cc, op, colors[3 * tid + 0], colors[3 * tid + 1]);
        gc.f2 = make_float4(colors[3 * tid + 2], 1.0f / fmaxf(depth, 1e-6f),
                            0.0f, 0.0f);
        g_core[pos] = gc;
        // unique stable key: (depth_bits, orig_idx, slot); depth>0.2 so the
        // float bit pattern is order-preserving as unsigned.
        g_skey[pos] = ((unsigned long long)__float_as_uint(depth) << 18)
                    | ((unsigned long long)tid << 9);
    }
    __syncthreads();
    if (tid == 0) g_count_dev = s_cnt;
}

// ---------------------------------------------------------------------------
// Kernel 2: tiled rasterization. 16x16 px tile per CTA (256 threads).
// Ballot tile-cull -> tiny block rank-sort of survivors -> per-pixel blend.
// ---------------------------------------------------------------------------
__global__ __launch_bounds__(256)
void raster_kernel(const float* __restrict__ bg,
                   const float* __restrict__ mask,
                   float* __restrict__ out)
{
    __shared__ unsigned long long s_srt[MAXN];
    __shared__ unsigned short    s_ord[MAXN];
    __shared__ int s_cnt;

    const int t = threadIdx.x;
    if (t == 0) s_cnt = 0;
    __syncthreads();

    const int count = g_count_dev;
    const float tx0 = (float)(blockIdx.x * 16);
    const float tx1 = tx0 + 15.0f;
    const float ty0 = (float)(blockIdx.y * 16);
    const float ty1 = ty0 + 15.0f;

    // Tile cull with ballot compaction (order-free).
    for (int base = 0; base < count; base += 256) {
        const int gi = base + t;
        bool fl = false;
        float4 bb;
        if (gi < count) {
            bb = g_bbox[gi];
            fl = (bb.y >= tx0) && (bb.x <= tx1) && (bb.w >= ty0) && (bb.z <= ty1);
        }
        const unsigned m = __ballot_sync(0xffffffffu, fl);
        int wbase = 0;
        if ((t & 31) == 0 && m) wbase = atomicAdd(&s_cnt, __popc(m));
        wbase = __shfl_sync(0xffffffffu, wbase, 0);
        if (fl)
            s_srt[wbase + __popc(m & ((1u << (t & 31)) - 1u))] =
                g_skey[gi] | (unsigned long long)gi;
    }
    __syncthreads();
    const int cnt = s_cnt;

    // Rank-sort survivors by unique (depth, orig_idx, slot) key.
    for (int i = t; i < cnt; i += 256) {
        const unsigned long long k = s_srt[i];
        int r = 0;
        for (int j = 0; j < cnt; j++) r += (s_srt[j] < k);
        s_ord[r] = (unsigned short)(k & 511ull);
    }
    __syncthreads();

    // Per-pixel front-to-back blend (exact reference keep tests).
    const int pxi = blockIdx.x * 16 + (t & 15);
    const int pyi = blockIdx.y * 16 + (t >> 4);
    const float xf = (float)pxi;
    const float yf = (float)pyi;

    float Tacc = 1.0f;
    float cr = 0.0f, cg = 0.0f, cbl = 0.0f, iv = 0.0f;

    for (int j = 0; j < cnt; j++) {
        const int gi = s_ord[j];
        const float4 f0 = __ldg(&g_core[gi].f0);
        const float4 f1 = __ldg(&g_core[gi].f1);
        const float4 f2 = __ldg(&g_core[gi].f2);
        const float dx = xf - f0.x;
        const float dy = yf - f0.y;
        const float power = -0.5f * (f0.z * dx * dx + f1.x * dy * dy)
                            - f0.w * dx * dy;
        if (power <= 0.0f) {
            const float alpha = fminf(0.99f, f1.y * __expf(power));
            if (alpha >= (1.0f / 255.0f)) {
                const float wgt = alpha * Tacc;
                cr  += wgt * f1.z;
                cg  += wgt * f1.w;
                cbl += wgt * f2.x;
                iv  += wgt * f2.y;
                Tacc *= (1.0f - alpha);
            }
        }
    }

    const int pix = pyi * IMG_W + pxi;
    const float mk = mask[pix];
    out[pix]            = (cr  + Tacc * bg[0]) * mk;
    out[HW + pix]       = (cg  + Tacc * bg[1]) * mk;
    out[2 * HW + pix]   = (cbl + Tacc * bg[2]) * mk;
    out[OFF_INVD + pix] = iv * mk;
}

// ---------------------------------------------------------------------------
extern "C" void kernel_launch(void* const* d_in, const int* in_sizes, int n_in,
                              void* d_out, int out_size)
{
    const float* means3D = (const float*)d_in[0];
    // d_in[1] = means2D (unused by the reference math)
    const float* opac    = (const float*)d_in[2];
    const float* colors  = (const float*)d_in[3];
    const float* scales  = (const float*)d_in[4];
    const float* rots    = (const float*)d_in[5];
    const float* Vm      = (const float*)d_in[6];
    const float* Pm      = (const float*)d_in[7];
    const float* bg      = (const float*)d_in[8];
    const float* mask    = (const float*)d_in[9];
    float* out = (float*)d_out;

    int n = in_sizes[0] / 3;
    if (n > MAXN) n = MAXN;

    prep_kernel<<<1, MAXN>>>(means3D, opac, colors, scales, rots, Vm, Pm,
                             out + OFF_RADII, n);
    raster_kernel<<<dim3(IMG_W / 16, IMG_H / 16), 256>>>(bg, mask, out);
}

// round 4
// speedup vs baseline: 2.0388x; 1.4328x over previous
#include <cuda_runtime.h>
#include <math.h>

// Problem constants (fixed by the reference)
#define IMG_W 256
#define IMG_H 256
#define MAXN  512
#define HW    (IMG_W * IMG_H)        // 65536
#define FX    256.0f                  // W / (2 * tanfovx)
#define FY    256.0f
#define LIMX  0.65f                   // 1.3 * tanfovx
#define LIMY  0.65f

#define TILE_W 32
#define TILE_H 16
#define NTHREADS 512                  // TILE_W * TILE_H

// Output layout in d_out (float32): color [3*HW], radii [MAXN], invd [HW]
#define OFF_RADII (3 * HW)
#define OFF_INVD  (3 * HW + MAXN)

// Blend core: 48 bytes = 3 float4
//   f0 = (px, py, ca, cb)   f1 = (cc, op, cr, cg)   f2 = (cbl, invd, 0, 0)
struct __align__(16) GCore { float4 f0, f1, f2; };

// ---------------------------------------------------------------------------
// Single fused kernel: every CTA redundantly preps all N gaussians (1/thread),
// culls against its own 32x16 tile into shared, rank-sorts the survivors by
// (depth, index) to reproduce the reference argsort order exactly, then
// alpha-blends per pixel from shared. One wave (128 CTAs), 4 barriers.
// ---------------------------------------------------------------------------
__global__ __launch_bounds__(NTHREADS)
void fused_raster_kernel(const float* __restrict__ means3D,
                         const float* __restrict__ opac,
                         const float* __restrict__ colors,
                         const float* __restrict__ scales,
                         const float* __restrict__ rots,
                         const float* __restrict__ Vm,   // 4x4 row-major
                         const float* __restrict__ Pm,   // 4x4 row-major
                         const float* __restrict__ bg,
                         const float* __restrict__ mask,
                         float* __restrict__ out,
                         int n)
{
    __shared__ int                s_cnt;
    __shared__ unsigned long long s_key[MAXN];   // (depth_bits<<32)|gid
    __shared__ GCore              s_core[MAXN];
    __shared__ unsigned short     s_ord[MAXN];

    const int t = threadIdx.x;
    if (t == 0) s_cnt = 0;
    __syncthreads();

    const float tx0 = (float)(blockIdx.x * TILE_W);
    const float tx1 = tx0 + (float)(TILE_W - 1);
    const float ty0 = (float)(blockIdx.y * TILE_H);
    const float ty1 = ty0 + (float)(TILE_H - 1);

    // ---- per-gaussian preprocess (thread t -> gaussian t) ----
    bool push = false;
    float depth = 0.0f, radii_val = 0.0f;
    float px = 0.f, py = 0.f, ca = 0.f, cbv = 0.f, cc = 0.f, op = 0.f;

    if (t < n) {
        const float m0 = means3D[3 * t + 0];
        const float m1 = means3D[3 * t + 1];
        const float m2 = means3D[3 * t + 2];

        // view transform t = V * [m,1]
        const float v0 = Vm[0] * m0 + Vm[1] * m1 + Vm[2]  * m2 + Vm[3];
        const float v1 = Vm[4] * m0 + Vm[5] * m1 + Vm[6]  * m2 + Vm[7];
        const float v2 = Vm[8] * m0 + Vm[9] * m1 + Vm[10] * m2 + Vm[11];
        depth = v2;

        // clip = P * [m,1]
        const float c0 = Pm[0]  * m0 + Pm[1]  * m1 + Pm[2]  * m2 + Pm[3];
        const float c1 = Pm[4]  * m0 + Pm[5]  * m1 + Pm[6]  * m2 + Pm[7];
        const float c3 = Pm[12] * m0 + Pm[13] * m1 + Pm[14] * m2 + Pm[15];
        const float pw = 1.0f / (c3 + 1e-7f);
        px = ((c0 * pw + 1.0f) * (float)IMG_W - 1.0f) * 0.5f;
        py = ((c1 * pw + 1.0f) * (float)IMG_H - 1.0f) * 0.5f;

        // quaternion -> rotation
        const float q0r = rots[4 * t + 0];
        const float q1r = rots[4 * t + 1];
        const float q2r = rots[4 * t + 2];
        const float q3r = rots[4 * t + 3];
        const float qn = rsqrtf(q0r*q0r + q1r*q1r + q2r*q2r + q3r*q3r);
        const float w = q0r * qn, x = q1r * qn, y = q2r * qn, z = q3r * qn;

        const float r00 = 1.0f - 2.0f * (y*y + z*z);
        const float r01 = 2.0f * (x*y - w*z);
        const float r02 = 2.0f * (x*z + w*y);
        const float r10 = 2.0f * (x*y + w*z);
        const float r11 = 1.0f - 2.0f * (x*x + z*z);
        const float r12 = 2.0f * (y*z - w*x);
        const float r20 = 2.0f * (x*z - w*y);
        const float r21 = 2.0f * (y*z + w*x);
        const float r22 = 1.0f - 2.0f * (x*x + y*y);

        const float s0 = scales[3 * t + 0];
        const float s1 = scales[3 * t + 1];
        const float s2 = scales[3 * t + 2];

        // M = R * diag(s); cov3d = M M^T (symmetric)
        const float M00 = r00*s0, M01 = r01*s1, M02 = r02*s2;
        const float M10 = r10*s0, M11 = r11*s1, M12 = r12*s2;
        const float M20 = r20*s0, M21 = r21*s1, M22 = r22*s2;
        const float C00 = M00*M00 + M01*M01 + M02*M02;
        const float C01 = M00*M10 + M01*M11 + M02*M12;
        const float C02 = M00*M20 + M01*M21 + M02*M22;
        const float C11 = M10*M10 + M11*M11 + M12*M12;
        const float C12 = M10*M20 + M11*M21 + M12*M22;
        const float C22 = M20*M20 + M21*M21 + M22*M22;

        // Jacobian
        const float tz = depth;
        const float itz = 1.0f / tz;
        const float txc = fminf(fmaxf(v0 * itz, -LIMX), LIMX) * tz;
        const float tyc = fminf(fmaxf(v1 * itz, -LIMY), LIMY) * tz;
        const float j00 = FX * itz;
        const float j02 = -FX * txc * itz * itz;
        const float j11 = FY * itz;
        const float j12 = -FY * tyc * itz * itz;

        // Tm = J * V[:3,:3]  (rows 0,1 only)
        const float T00 = j00 * Vm[0] + j02 * Vm[8];
        const float T01 = j00 * Vm[1] + j02 * Vm[9];
        const float T02 = j00 * Vm[2] + j02 * Vm[10];
        const float T10 = j11 * Vm[4] + j12 * Vm[8];
        const float T11 = j11 * Vm[5] + j12 * Vm[9];
        const float T12 = j11 * Vm[6] + j12 * Vm[10];

        // cov2d = Tm * C * Tm^T
        const float u0 = C00*T00 + C01*T01 + C02*T02;
        const float u1 = C01*T00 + C11*T01 + C12*T02;
        const float u2 = C02*T00 + C12*T01 + C22*T02;
        const float cxx = T00*u0 + T01*u1 + T02*u2;
        const float cxy = T10*u0 + T11*u1 + T12*u2;
        const float w0 = C00*T10 + C01*T11 + C02*T12;
        const float w1 = C01*T10 + C11*T11 + C12*T12;
        const float w2 = C02*T10 + C12*T11 + C22*T12;
        const float cyy = T10*w0 + T11*w1 + T12*w2;

        const float a = cxx + 0.3f;
        const float b = cxy;
        const float c = cyy + 0.3f;
        const float det = a * c - b * b;
        const float inv_det = 1.0f / ((det != 0.0f) ? det : 1.0f);
        ca  = c * inv_det;
        cbv = -b * inv_det;
        cc  = a * inv_det;
        const float mid = 0.5f * (a + c);
        const float lam = mid + sqrtf(fmaxf(mid * mid - det, 0.1f));
        radii_val = ceilf(3.0f * sqrtf(lam));

        const bool valid = (depth > 0.2f) && (det > 0.0f);
        op = opac[t];

        // keep (alpha>=1/255, power<=0) => mahal^2 <= qmax = 2*ln(255*op);
        // extent along x of that ellipse is sqrt(qmax*a), along y sqrt(qmax*c)
        // (conic determinant identity). +1 px slack; exact tests per pixel.
        const float qmax = 2.0f * logf(255.0f * op);
        if (valid && qmax > 0.0f) {
            const float dxm = sqrtf(qmax * a) + 1.0f;
            const float dym = sqrtf(qmax * c) + 1.0f;
            push = (px + dxm >= tx0) && (px - dxm <= tx1) &&
                   (py + dym >= ty0) && (py - dym <= ty1);
        }
    }

    // ---- ballot compaction of this tile's survivors into shared ----
    const unsigned m = __ballot_sync(0xffffffffu, push);
    const int lane = t & 31;
    int wbase = 0;
    if (lane == 0 && m) wbase = atomicAdd(&s_cnt, __popc(m));
    wbase = __shfl_sync(0xffffffffu, wbase, 0);
    if (push) {
        const int pos = wbase + __popc(m & ((1u << lane) - 1u));
        s_key[pos] = ((unsigned long long)__float_as_uint(depth) << 32)
                   | (unsigned long long)t;
        GCore gc;
        gc.f0 = make_float4(px, py, ca, cbv);
        gc.f1 = make_float4(cc, op, colors[3 * t + 0], colors[3 * t + 1]);
        gc.f2 = make_float4(colors[3 * t + 2], 1.0f / fmaxf(depth, 1e-6f),
                            0.0f, 0.0f);
        s_core[pos] = gc;
    }

    // radii output (identical in every CTA; block (0,0) writes)
    if (blockIdx.x == 0 && blockIdx.y == 0 && t < n)
        out[OFF_RADII + t] = radii_val;

    __syncthreads();
    const int cnt = s_cnt;

    // ---- rank-sort survivors by unique (depth_bits, gid) key ----
    for (int i = t; i < cnt; i += NTHREADS) {
        const unsigned long long k = s_key[i];
        int r = 0;
        for (int j = 0; j < cnt; j++) r += (s_key[j] < k);
        s_ord[r] = (unsigned short)i;
    }
    __syncthreads();

    // ---- per-pixel front-to-back blend (exact reference keep tests) ----
    const int pxi = blockIdx.x * TILE_W + (t & (TILE_W - 1));
    const int pyi = blockIdx.y * TILE_H + (t / TILE_W);
    const float xf = (float)pxi;
    const float yf = (float)pyi;

    float Tacc = 1.0f;
    float cr = 0.0f, cg = 0.0f, cbl = 0.0f, iv = 0.0f;

    for (int j = 0; j < cnt; j++) {
        const GCore& g = s_core[s_ord[j]];
        const float4 f0 = g.f0;
        const float4 f1 = g.f1;
        const float4 f2 = g.f2;
        const float dx = xf - f0.x;
        const float dy = yf - f0.y;
        const float power = -0.5f * (f0.z * dx * dx + f1.x * dy * dy)
                            - f0.w * dx * dy;
        if (power <= 0.0f) {
            const float alpha = fminf(0.99f, f1.y * __expf(power));
            if (alpha >= (1.0f / 255.0f)) {
                const float wgt = alpha * Tacc;
                cr  += wgt * f1.z;
                cg  += wgt * f1.w;
                cbl += wgt * f2.x;
                iv  += wgt * f2.y;
                Tacc *= (1.0f - alpha);
            }
        }
    }

    const int pix = pyi * IMG_W + pxi;
    const float mk = __ldg(&mask[pix]);
    const float b0 = __ldg(&bg[0]);
    const float b1 = __ldg(&bg[1]);
    const float b2 = __ldg(&bg[2]);
    out[pix]            = (cr  + Tacc * b0) * mk;
    out[HW + pix]       = (cg  + Tacc * b1) * mk;
    out[2 * HW + pix]   = (cbl + Tacc * b2) * mk;
    out[OFF_INVD + pix] = iv * mk;
}

// ---------------------------------------------------------------------------
extern "C" void kernel_launch(void* const* d_in, const int* in_sizes, int n_in,
                              void* d_out, int out_size)
{
    const float* means3D = (const float*)d_in[0];
    // d_in[1] = means2D (unused by the reference math)
    const float* opac    = (const float*)d_in[2];
    const float* colors  = (const float*)d_in[3];
    const float* scales  = (const float*)d_in[4];
    const float* rots    = (const float*)d_in[5];
    const float* Vm      = (const float*)d_in[6];
    const float* Pm      = (const float*)d_in[7];
    const float* bg      = (const float*)d_in[8];
    const float* mask    = (const float*)d_in[9];
    float* out = (float*)d_out;

    int n = in_sizes[0] / 3;
    if (n > MAXN) n = MAXN;

    fused_raster_kernel<<<dim3(IMG_W / TILE_W, IMG_H / TILE_H), NTHREADS>>>(
        means3D, opac, colors, scales, rots, Vm, Pm, bg, mask, out, n);
}

// round 5
// speedup vs baseline: 2.3074x; 1.1318x over previous
#include <cuda_runtime.h>
#include <math.h>

// Problem constants (fixed by the reference)
#define IMG_W 256
#define IMG_H 256
#define MAXN  512
#define HW    (IMG_W * IMG_H)        // 65536
#define FX    256.0f                  // W / (2 * tanfovx)
#define FY    256.0f
#define LIMX  0.65f                   // 1.3 * tanfovx
#define LIMY  0.65f

#define TILE_W 32
#define TILE_H 16
#define NTHREADS 512                  // TILE_W * TILE_H

// Output layout in d_out (float32): color [3*HW], radii [MAXN], invd [HW]
#define OFF_RADII (3 * HW)
#define OFF_INVD  (3 * HW + MAXN)

// Blend core: 48 bytes = 3 float4
//   f0 = (px, py, ca, cb)   f1 = (cc, op, cr, cg)   f2 = (cbl, invd, 0, 0)
struct __align__(16) GCore { float4 f0, f1, f2; };

// ---------------------------------------------------------------------------
// Single fused kernel: every CTA redundantly preps all N gaussians (1/thread),
// culls against its own 32x16 tile into shared, rank-sorts the survivors by
// (depth, index) so compositing order is bit-identical to argsort(depth),
// then alpha-blends per pixel from shared with a 4-wide unrolled loop.
// ---------------------------------------------------------------------------
__global__ __launch_bounds__(NTHREADS)
void fused_raster_kernel(const float* __restrict__ means3D,
                         const float* __restrict__ opac,
                         const float* __restrict__ colors,
                         const float* __restrict__ scales,
                         const float* __restrict__ rots,
                         const float* __restrict__ Vm,   // 4x4 row-major
                         const float* __restrict__ Pm,   // 4x4 row-major
                         const float* __restrict__ bg,
                         const float* __restrict__ mask,
                         float* __restrict__ out,
                         int n)
{
    __shared__ int                s_cnt;
    __shared__ unsigned long long s_key[MAXN];   // (depth_bits<<32)|gid
    __shared__ GCore              s_core[MAXN];
    __shared__ unsigned short     s_ord[MAXN + 4];

    const int t = threadIdx.x;
    if (t == 0) s_cnt = 0;
    __syncthreads();

    const float tx0 = (float)(blockIdx.x * TILE_W);
    const float tx1 = tx0 + (float)(TILE_W - 1);
    const float ty0 = (float)(blockIdx.y * TILE_H);
    const float ty1 = ty0 + (float)(TILE_H - 1);

    // ---- per-gaussian preprocess (thread t -> gaussian t) ----
    bool push = false;
    float depth = 0.0f, radii_val = 0.0f;
    float px = 0.f, py = 0.f, ca = 0.f, cbv = 0.f, cc = 0.f, op = 0.f;

    if (t < n) {
        const float m0 = means3D[3 * t + 0];
        const float m1 = means3D[3 * t + 1];
        const float m2 = means3D[3 * t + 2];

        // view transform t = V * [m,1]
        const float v0 = Vm[0] * m0 + Vm[1] * m1 + Vm[2]  * m2 + Vm[3];
        const float v1 = Vm[4] * m0 + Vm[5] * m1 + Vm[6]  * m2 + Vm[7];
        const float v2 = Vm[8] * m0 + Vm[9] * m1 + Vm[10] * m2 + Vm[11];
        depth = v2;

        // clip = P * [m,1]
        const float c0 = Pm[0]  * m0 + Pm[1]  * m1 + Pm[2]  * m2 + Pm[3];
        const float c1 = Pm[4]  * m0 + Pm[5]  * m1 + Pm[6]  * m2 + Pm[7];
        const float c3 = Pm[12] * m0 + Pm[13] * m1 + Pm[14] * m2 + Pm[15];
        const float pw = 1.0f / (c3 + 1e-7f);
        px = ((c0 * pw + 1.0f) * (float)IMG_W - 1.0f) * 0.5f;
        py = ((c1 * pw + 1.0f) * (float)IMG_H - 1.0f) * 0.5f;

        // quaternion -> rotation (one vectorized load)
        const float4 q4 = *reinterpret_cast<const float4*>(&rots[4 * t]);
        const float qn = rsqrtf(q4.x*q4.x + q4.y*q4.y + q4.z*q4.z + q4.w*q4.w);
        const float w = q4.x * qn, x = q4.y * qn, y = q4.z * qn, z = q4.w * qn;

        const float r00 = 1.0f - 2.0f * (y*y + z*z);
        const float r01 = 2.0f * (x*y - w*z);
        const float r02 = 2.0f * (x*z + w*y);
        const float r10 = 2.0f * (x*y + w*z);
        const float r11 = 1.0f - 2.0f * (x*x + z*z);
        const float r12 = 2.0f * (y*z - w*x);
        const float r20 = 2.0f * (x*z - w*y);
        const float r21 = 2.0f * (y*z + w*x);
        const float r22 = 1.0f - 2.0f * (x*x + y*y);

        const float s0 = scales[3 * t + 0];
        const float s1 = scales[3 * t + 1];
        const float s2 = scales[3 * t + 2];

        // M = R * diag(s); cov3d = M M^T (symmetric)
        const float M00 = r00*s0, M01 = r01*s1, M02 = r02*s2;
        const float M10 = r10*s0, M11 = r11*s1, M12 = r12*s2;
        const float M20 = r20*s0, M21 = r21*s1, M22 = r22*s2;
        const float C00 = M00*M00 + M01*M01 + M02*M02;
        const float C01 = M00*M10 + M01*M11 + M02*M12;
        const float C02 = M00*M20 + M01*M21 + M02*M22;
        const float C11 = M10*M10 + M11*M11 + M12*M12;
        const float C12 = M10*M20 + M11*M21 + M12*M22;
        const float C22 = M20*M20 + M21*M21 + M22*M22;

        // Jacobian
        const float tz = depth;
        const float itz = 1.0f / tz;
        const float txc = fminf(fmaxf(v0 * itz, -LIMX), LIMX) * tz;
        const float tyc = fminf(fmaxf(v1 * itz, -LIMY), LIMY) * tz;
        const float j00 = FX * itz;
        const float j02 = -FX * txc * itz * itz;
        const float j11 = FY * itz;
        const float j12 = -FY * tyc * itz * itz;

        // Tm = J * V[:3,:3]  (rows 0,1 only)
        const float T00 = j00 * Vm[0] + j02 * Vm[8];
        const float T01 = j00 * Vm[1] + j02 * Vm[9];
        const float T02 = j00 * Vm[2] + j02 * Vm[10];
        const float T10 = j11 * Vm[4] + j12 * Vm[8];
        const float T11 = j11 * Vm[5] + j12 * Vm[9];
        const float T12 = j11 * Vm[6] + j12 * Vm[10];

        // cov2d = Tm * C * Tm^T
        const float u0 = C00*T00 + C01*T01 + C02*T02;
        const float u1 = C01*T00 + C11*T01 + C12*T02;
        const float u2 = C02*T00 + C12*T01 + C22*T02;
        const float cxx = T00*u0 + T01*u1 + T02*u2;
        const float cxy = T10*u0 + T11*u1 + T12*u2;
        const float w0 = C00*T10 + C01*T11 + C02*T12;
        const float w1 = C01*T10 + C11*T11 + C12*T12;
        const float w2 = C02*T10 + C12*T11 + C22*T12;
        const float cyy = T10*w0 + T11*w1 + T12*w2;

        const float a = cxx + 0.3f;
        const float b = cxy;
        const float c = cyy + 0.3f;
        const float det = a * c - b * b;
        const float inv_det = 1.0f / ((det != 0.0f) ? det : 1.0f);
        ca  = c * inv_det;
        cbv = -b * inv_det;
        cc  = a * inv_det;
        const float mid = 0.5f * (a + c);
        const float lam = mid + sqrtf(fmaxf(mid * mid - det, 0.1f));
        radii_val = ceilf(3.0f * sqrtf(lam));

        const bool valid = (depth > 0.2f) && (det > 0.0f);
        op = opac[t];

        // keep (alpha>=1/255, power<=0) => mahal^2 <= qmax = 2*ln(255*op);
        // extent along x is sqrt(qmax*a), along y sqrt(qmax*c) (conic det
        // identity). +1 px slack; exact tests run per pixel.
        const float qmax = 2.0f * logf(255.0f * op);
        if (valid && qmax > 0.0f) {
            const float dxm = sqrtf(qmax * a) + 1.0f;
            const float dym = sqrtf(qmax * c) + 1.0f;
            push = (px + dxm >= tx0) && (px - dxm <= tx1) &&
                   (py + dym >= ty0) && (py - dym <= ty1);
        }
    }

    // ---- ballot compaction of this tile's survivors into shared ----
    const unsigned m = __ballot_sync(0xffffffffu, push);
    const int lane = t & 31;
    int wbase = 0;
    if (lane == 0 && m) wbase = atomicAdd(&s_cnt, __popc(m));
    wbase = __shfl_sync(0xffffffffu, wbase, 0);
    if (push) {
        const int pos = wbase + __popc(m & ((1u << lane) - 1u));
        s_key[pos] = ((unsigned long long)__float_as_uint(depth) << 32)
                   | (unsigned long long)t;
        GCore gc;
        gc.f0 = make_float4(px, py, ca, cbv);
        gc.f1 = make_float4(cc, op, colors[3 * t + 0], colors[3 * t + 1]);
        gc.f2 = make_float4(colors[3 * t + 2], 1.0f / fmaxf(depth, 1e-6f),
                            0.0f, 0.0f);
        s_core[pos] = gc;
    }

    // radii output (identical in every CTA; block (0,0) writes)
    if (blockIdx.x == 0 && blockIdx.y == 0 && t < n)
        out[OFF_RADII + t] = radii_val;

    __syncthreads();
    const int cnt = s_cnt;

    // ---- rank-sort survivors by unique (depth_bits, gid) key ----
    for (int i = t; i < cnt; i += NTHREADS) {
        const unsigned long long k = s_key[i];
        int r = 0;
        for (int j = 0; j < cnt; j++) r += (s_key[j] < k);
        s_ord[r] = (unsigned short)i;
    }
    // pad so the unrolled loop's ushort4 load is always in-bounds
    if (t < 4) s_ord[cnt + t] = 0;
    __syncthreads();

    // ---- per-pixel front-to-back blend, 4-wide unrolled ----
    const int pxi = blockIdx.x * TILE_W + (t & (TILE_W - 1));
    const int pyi = blockIdx.y * TILE_H + (t / TILE_W);
    const float xf = (float)pxi;
    const float yf = (float)pyi;

    float Tacc = 1.0f;
    float cr = 0.0f, cg = 0.0f, cbl = 0.0f, iv = 0.0f;

    int j = 0;
    const int cnt4 = cnt & ~3;
    for (; j < cnt4; j += 4) {
        // 4 indices in one 64-bit LDS (j is 4-aligned, s_ord padded)
        const ushort4 o4 = *reinterpret_cast<const ushort4*>(&s_ord[j]);

        const GCore g0 = s_core[o4.x];
        const GCore g1 = s_core[o4.y];
        const GCore g2 = s_core[o4.z];
        const GCore g3 = s_core[o4.w];

        // independent alpha computations (masked to 0 when keep tests fail)
        float al[4];
        {
            const float dx = xf - g0.f0.x, dy = yf - g0.f0.y;
            const float p = -0.5f * (g0.f0.z*dx*dx + g0.f1.x*dy*dy) - g0.f0.w*dx*dy;
            const float a = fminf(0.99f, g0.f1.y * __expf(p));
            al[0] = (p <= 0.0f && a >= (1.0f/255.0f)) ? a : 0.0f;
        }
        {
            const float dx = xf - g1.f0.x, dy = yf - g1.f0.y;
            const float p = -0.5f * (g1.f0.z*dx*dx + g1.f1.x*dy*dy) - g1.f0.w*dx*dy;
            const float a = fminf(0.99f, g1.f1.y * __expf(p));
            al[1] = (p <= 0.0f && a >= (1.0f/255.0f)) ? a : 0.0f;
        }
        {
            const float dx = xf - g2.f0.x, dy = yf - g2.f0.y;
            const float p = -0.5f * (g2.f0.z*dx*dx + g2.f1.x*dy*dy) - g2.f0.w*dx*dy;
            const float a = fminf(0.99f, g2.f1.y * __expf(p));
            al[2] = (p <= 0.0f && a >= (1.0f/255.0f)) ? a : 0.0f;
        }
        {
            const float dx = xf - g3.f0.x, dy = yf - g3.f0.y;
            const float p = -0.5f * (g3.f0.z*dx*dx + g3.f1.x*dy*dy) - g3.f0.w*dx*dy;
            const float a = fminf(0.99f, g3.f1.y * __expf(p));
            al[3] = (p <= 0.0f && a >= (1.0f/255.0f)) ? a : 0.0f;
        }

        // short serial accumulate (alpha==0 is an exact no-op)
        float wgt;
        wgt = al[0] * Tacc;
        cr += wgt * g0.f1.z; cg += wgt * g0.f1.w;
        cbl += wgt * g0.f2.x; iv += wgt * g0.f2.y;
        Tacc *= (1.0f - al[0]);
        wgt = al[1] * Tacc;
        cr += wgt * g1.f1.z; cg += wgt * g1.f1.w;
        cbl += wgt * g1.f2.x; iv += wgt * g1.f2.y;
        Tacc *= (1.0f - al[1]);
        wgt = al[2] * Tacc;
        cr += wgt * g2.f1.z; cg += wgt * g2.f1.w;
        cbl += wgt * g2.f2.x; iv += wgt * g2.f2.y;
        Tacc *= (1.0f - al[2]);
        wgt = al[3] * Tacc;
        cr += wgt * g3.f1.z; cg += wgt * g3.f1.w;
        cbl += wgt * g3.f2.x; iv += wgt * g3.f2.y;
        Tacc *= (1.0f - al[3]);
    }
    for (; j < cnt; j++) {
        const GCore& g = s_core[s_ord[j]];
        const float dx = xf - g.f0.x, dy = yf - g.f0.y;
        const float p = -0.5f * (g.f0.z*dx*dx + g.f1.x*dy*dy) - g.f0.w*dx*dy;
        if (p <= 0.0f) {
            const float a = fminf(0.99f, g.f1.y * __expf(p));
            if (a >= (1.0f/255.0f)) {
                const float wgt = a * Tacc;
                cr += wgt * g.f1.z; cg += wgt * g.f1.w;
                cbl += wgt * g.f2.x; iv += wgt * g.f2.y;
                Tacc *= (1.0f - a);
            }
        }
    }

    const int pix = pyi * IMG_W + pxi;
    const float mk = __ldg(&mask[pix]);
    const float b0 = __ldg(&bg[0]);
    const float b1 = __ldg(&bg[1]);
    const float b2 = __ldg(&bg[2]);
    out[pix]            = (cr  + Tacc * b0) * mk;
    out[HW + pix]       = (cg  + Tacc * b1) * mk;
    out[2 * HW + pix]   = (cbl + Tacc * b2) * mk;
    out[OFF_INVD + pix] = iv * mk;
}

// ---------------------------------------------------------------------------
extern "C" void kernel_launch(void* const* d_in, const int* in_sizes, int n_in,
                              void* d_out, int out_size)
{
    const float* means3D = (const float*)d_in[0];
    // d_in[1] = means2D (unused by the reference math)
    const float* opac    = (const float*)d_in[2];
    const float* colors  = (const float*)d_in[3];
    const float* scales  = (const float*)d_in[4];
    const float* rots    = (const float*)d_in[5];
    const float* Vm      = (const float*)d_in[6];
    const float* Pm      = (const float*)d_in[7];
    const float* bg      = (const float*)d_in[8];
    const float* mask    = (const float*)d_in[9];
    float* out = (float*)d_out;

    int n = in_sizes[0] / 3;
    if (n > MAXN) n = MAXN;

    fused_raster_kernel<<<dim3(IMG_W / TILE_W, IMG_H / TILE_H), NTHREADS>>>(
        means3D, opac, colors, scales, rots, Vm, Pm, bg, mask, out, n);
}